// round 2
// baseline (speedup 1.0000x reference)
#include <cuda_runtime.h>
#include <cuda_bf16.h>
#include <math.h>
#include <stdint.h>

// ---------------- problem constants ----------------
#define BIMG 8
#define OPI_ 64
#define RPI_ 1024
#define NN 512            // N objects
#define RR 8192           // R relations
#define OBJD 4096
#define HD 512
#define NOC_ 151
#define NRC_ 51
#define TSTEPS 3
#define IOU_THR_ 0.3f

// ---------------- scratch (device globals; no runtime alloc allowed) -------
__device__ float g_obj_probs[NN * NOC_];
__device__ float g_fo[NN * HD];
__device__ float g_h_obj[NN * HD];
__device__ float g_h_rel[RR * HD];
__device__ float g_sumso[RR * HD];
__device__ float g_m_rel[RR * HD];
__device__ float g_hm[RR * HD];
__device__ float g_m_obj[NN * HD];
__device__ float g_xw_rel[RR * 3 * HD];
__device__ float g_hu_rel[RR * 2 * HD];
__device__ float g_z_rel[RR * HD];
__device__ float g_rh_rel[RR * HD];
__device__ float g_nu_rel[RR * HD];
__device__ float g_xw_obj[NN * 3 * HD];
__device__ float g_hu_obj[NN * 2 * HD];
__device__ float g_z_obj[NN * HD];
__device__ float g_rh_obj[NN * HD];
__device__ float g_nu_obj[NN * HD];
__device__ float g_sp[NN * NOC_];
__device__ unsigned char g_keep[150 * NN];
__device__ int g_s_idx[RR];
__device__ int g_o_idx[RR];

// ---------------- generic fp32 SGEMM: C = A@B (+bias) (+addm) --------------
// 128x128 block tile, BK=8, 256 threads, 8x8 per-thread microtile.
__global__ __launch_bounds__(256) void sgemm_kernel(
    const float* __restrict__ A, int lda,
    const float* __restrict__ B, int ldb,
    float* __restrict__ C, int ldc,
    int M, int N, int K,
    const float* __restrict__ bias,   // length N or null
    const float* __restrict__ addm)   // [M, ldc] or null
{
    __shared__ float As[8][132];
    __shared__ float Bs[8][128];
    const int tid = threadIdx.x;
    const int tx = tid & 15;
    const int ty = tid >> 4;
    const int m0 = blockIdx.y * 128;
    const int n0 = blockIdx.x * 128;

    float acc[8][8];
#pragma unroll
    for (int i = 0; i < 8; i++)
#pragma unroll
        for (int j = 0; j < 8; j++) acc[i][j] = 0.f;

    for (int k0 = 0; k0 < K; k0 += 8) {
        // A tile: rows m0..m0+127, cols k0..k0+7
#pragma unroll
        for (int l = 0; l < 4; l++) {
            int e = tid + l * 256;
            int r = e >> 3;
            int c = e & 7;
            float v = 0.f;
            int gm = m0 + r, gk = k0 + c;
            if (gm < M && gk < K) v = A[(size_t)gm * lda + gk];
            As[c][r] = v;
        }
        // B tile: rows k0..k0+7, cols n0..n0+127
#pragma unroll
        for (int l = 0; l < 4; l++) {
            int e = tid + l * 256;
            int r = e >> 7;
            int c = e & 127;
            float v = 0.f;
            int gk = k0 + r, gn = n0 + c;
            if (gk < K && gn < N) v = B[(size_t)gk * ldb + gn];
            Bs[r][c] = v;
        }
        __syncthreads();
#pragma unroll
        for (int k = 0; k < 8; k++) {
            float a[8], b[8];
#pragma unroll
            for (int i = 0; i < 8; i++) a[i] = As[k][ty * 8 + i];
#pragma unroll
            for (int j = 0; j < 8; j++) b[j] = Bs[k][tx * 8 + j];
#pragma unroll
            for (int i = 0; i < 8; i++)
#pragma unroll
                for (int j = 0; j < 8; j++)
                    acc[i][j] = fmaf(a[i], b[j], acc[i][j]);
        }
        __syncthreads();
    }
#pragma unroll
    for (int i = 0; i < 8; i++) {
        int gm = m0 + ty * 8 + i;
        if (gm >= M) continue;
#pragma unroll
        for (int j = 0; j < 8; j++) {
            int gn = n0 + tx * 8 + j;
            if (gn >= N) continue;
            float v = acc[i][j];
            if (bias) v += bias[gn];
            if (addm) v += addm[(size_t)gm * ldc + gn];
            C[(size_t)gm * ldc + gn] = v;
        }
    }
}

// ---------------- decode rel_inds (handles int64 OR int32 storage) ---------
__global__ __launch_bounds__(1024) void decode_rel_kernel(const void* rel_raw) {
    __shared__ int s_or;
    int tid = threadIdx.x;
    if (tid == 0) s_or = 0;
    __syncthreads();
    const int* v32 = (const int*)rel_raw;
    int acc = 0;
    // odd int32 positions among the first 3R int32 words:
    // int64 storage -> these are high words of nonneg values -> all zero.
    // int32 storage -> these are real indices -> some nonzero.
    for (int i = tid; i < (3 * RR) / 2; i += 1024) acc |= v32[2 * i + 1];
    if (acc) atomicOr(&s_or, 1);
    __syncthreads();
    bool is64 = (s_or == 0);
    if (is64) {
        const long long* v = (const long long*)rel_raw;
        for (int r = tid; r < RR; r += 1024) {
            g_s_idx[r] = (int)v[3 * r + 1];
            g_o_idx[r] = (int)v[3 * r + 2];
        }
    } else {
        for (int r = tid; r < RR; r += 1024) {
            g_s_idx[r] = v32[3 * r + 1];
            g_o_idx[r] = v32[3 * r + 2];
        }
    }
}

// ---------------- row softmax over NOC columns ------------------------------
__global__ void softmax_kernel(const float* __restrict__ X, float* __restrict__ Y) {
    int row = blockIdx.x;
    int tid = threadIdx.x;  // 256
    __shared__ float red[256];
    const float* x = X + (size_t)row * NOC_;
    float m = -3.4e38f;
    for (int c = tid; c < NOC_; c += 256) m = fmaxf(m, x[c]);
    red[tid] = m; __syncthreads();
    for (int s = 128; s > 0; s >>= 1) {
        if (tid < s) red[tid] = fmaxf(red[tid], red[tid + s]);
        __syncthreads();
    }
    m = red[0]; __syncthreads();
    float sum = 0.f;
    for (int c = tid; c < NOC_; c += 256) sum += expf(x[c] - m);
    red[tid] = sum; __syncthreads();
    for (int s = 128; s > 0; s >>= 1) {
        if (tid < s) red[tid] += red[tid + s];
        __syncthreads();
    }
    float inv = 1.f / red[0];
    for (int c = tid; c < NOC_; c += 256)
        Y[(size_t)row * NOC_ + c] = expf(x[c] - m) * inv;
}

// ---------------- SUMSO[r] = h_obj[s_r] + h_obj[o_r] ------------------------
__global__ void gather_sum_kernel(const float* __restrict__ Hobj, float* __restrict__ out) {
    int idx = blockIdx.x * blockDim.x + threadIdx.x;
    if (idx >= RR * HD) return;
    int r = idx >> 9;
    int c = idx & 511;
    int s = g_s_idx[r];
    int o = g_o_idx[r];
    out[idx] = Hobj[(size_t)s * HD + c] + Hobj[(size_t)o * HD + c];
}

// ---------------- m_obj scatter: deterministic block-per-object scan --------
__global__ __launch_bounds__(512) void scatter_obj_kernel(const float* __restrict__ HM,
                                                          float* __restrict__ MOBJ) {
    int obj = blockIdx.x;      // global object id 0..511
    int c = threadIdx.x;       // hidden dim 0..511
    int img = obj >> 6;
    int base = img * RPI_;
    __shared__ int ss[RPI_];
    __shared__ int oo[RPI_];
    for (int j = c; j < RPI_; j += 512) {
        ss[j] = g_s_idx[base + j];
        oo[j] = g_o_idx[base + j];
    }
    __syncthreads();
    float acc = 0.f;
    for (int j = 0; j < RPI_; j++) {
        if (ss[j] == obj) acc += HM[(size_t)(base + j) * HD + c];
        if (oo[j] == obj) acc += HM[(size_t)(base + j) * HD + c];
    }
    MOBJ[(size_t)obj * HD + c] = acc;
}

// ---------------- GRU elementwise: z, r*h ------------------------------------
__global__ void gru_zr_kernel(const float* __restrict__ XW, const float* __restrict__ HU,
                              const float* __restrict__ b, const float* __restrict__ Hh,
                              float* __restrict__ Z, float* __restrict__ RH, int M) {
    int idx = blockIdx.x * blockDim.x + threadIdx.x;
    if (idx >= M * HD) return;
    int row = idx >> 9;
    int c = idx & 511;
    float z = XW[(size_t)row * 1536 + c] + HU[(size_t)row * 1024 + c] + b[c];
    float r = XW[(size_t)row * 1536 + 512 + c] + HU[(size_t)row * 1024 + 512 + c] + b[512 + c];
    z = 1.f / (1.f + expf(-z));
    r = 1.f / (1.f + expf(-r));
    Z[idx] = z;
    RH[idx] = r * Hh[idx];
}

// ---------------- GRU elementwise: n, h update (in place) -------------------
__global__ void gru_fin_kernel(const float* __restrict__ XW, const float* __restrict__ NU,
                               const float* __restrict__ b, const float* __restrict__ Z,
                               float* __restrict__ Hh, int M) {
    int idx = blockIdx.x * blockDim.x + threadIdx.x;
    if (idx >= M * HD) return;
    int row = idx >> 9;
    int c = idx & 511;
    float n = tanhf(XW[(size_t)row * 1536 + 1024 + c] + NU[idx] + b[1024 + c]);
    float z = Z[idx];
    Hh[idx] = (1.f - z) * Hh[idx] + z * n;
}

// ---------------- NMS: one block per class (1..150) -------------------------
__global__ __launch_bounds__(512) void nms_kernel(const float* __restrict__ SP,
                                                  const float* __restrict__ BOX,
                                                  unsigned char* __restrict__ KEEP) {
    int cls = blockIdx.x + 1;   // class index 1..150
    int tid = threadIdx.x;      // 0..511
    __shared__ float sc[NN];
    __shared__ int sidx[NN];
    __shared__ float bx[NN][4];
    __shared__ float area[NN];
    __shared__ unsigned char keep[NN];

    sc[tid] = SP[(size_t)tid * NOC_ + cls];
    sidx[tid] = tid;
    __syncthreads();

    // bitonic sort, descending by score, stable (idx ascending tiebreak)
    for (int k = 2; k <= NN; k <<= 1) {
        for (int j = k >> 1; j > 0; j >>= 1) {
            int ixj = tid ^ j;
            if (ixj > tid) {
                float s1 = sc[tid], s2 = sc[ixj];
                int i1 = sidx[tid], i2 = sidx[ixj];
                bool dir = ((tid & k) == 0);
                bool precBA = (s2 > s1) || (s2 == s1 && i2 < i1);
                if (precBA == dir) {
                    sc[tid] = s2; sc[ixj] = s1;
                    sidx[tid] = i2; sidx[ixj] = i1;
                }
            }
            __syncthreads();
        }
    }

    int oi = sidx[tid];
    float x1 = BOX[((size_t)oi * NOC_ + cls) * 4 + 0];
    float y1 = BOX[((size_t)oi * NOC_ + cls) * 4 + 1];
    float x2 = BOX[((size_t)oi * NOC_ + cls) * 4 + 2];
    float y2 = BOX[((size_t)oi * NOC_ + cls) * 4 + 3];
    bx[tid][0] = x1; bx[tid][1] = y1; bx[tid][2] = x2; bx[tid][3] = y2;
    area[tid] = (x2 - x1) * (y2 - y1);
    keep[tid] = 1;
    __syncthreads();

    for (int i = 0; i < NN - 1; i++) {
        if (tid > i && keep[i] && keep[tid]) {
            float lx = fmaxf(bx[i][0], x1);
            float ly = fmaxf(bx[i][1], y1);
            float rx = fminf(bx[i][2], x2);
            float ry = fminf(bx[i][3], y2);
            float w = fmaxf(rx - lx, 0.f);
            float h = fmaxf(ry - ly, 0.f);
            float inter = w * h;
            float iou = inter / (area[i] + area[tid] - inter + 1e-9f);
            if (iou > IOU_THR_) keep[tid] = 0;
        }
        __syncthreads();
    }
    KEEP[(size_t)(cls - 1) * NN + oi] = keep[tid];
}

// ---------------- obj_preds: argmax over kept class scores ------------------
__global__ void preds_kernel(const float* __restrict__ SP, const unsigned char* __restrict__ KEEP,
                             float* __restrict__ out) {
    int n = blockIdx.x * blockDim.x + threadIdx.x;
    if (n >= NN) return;
    float best = -1.f;
    int bi = 0;
    for (int c = 0; c < 150; c++) {
        float v = KEEP[(size_t)c * NN + n] ? SP[(size_t)n * NOC_ + c + 1] : 0.f;
        if (v > best) { best = v; bi = c; }
    }
    out[n] = (float)(bi + 1);
}

// ---------------- host orchestration ----------------------------------------
static void sgemm(const float* A, int lda, const float* B, int ldb,
                  float* C, int ldc, int M, int N, int K,
                  const float* bias, const float* addm) {
    dim3 g((N + 127) / 128, (M + 127) / 128);
    sgemm_kernel<<<g, 256>>>(A, lda, B, ldb, C, ldc, M, N, K, bias, addm);
}

// One-time host-side cache of device-global addresses (pure pointer lookups,
// no device work, no allocation — safe before/under graph capture).
struct Scratch {
    float *OBJ_PROBS, *FO, *HOBJ, *HREL, *SUMSO, *MREL, *HM, *MOBJ;
    float *XWR, *HUR, *ZR, *RHR, *NUR, *XWO, *HUO, *ZO, *RHO, *NUO, *SP;
    unsigned char* KEEP;
    bool init = false;
};
static Scratch g_sc;

static void init_scratch() {
    if (g_sc.init) return;
    void* p;
#define GET(sym, fld, T) cudaGetSymbolAddress(&p, sym); g_sc.fld = (T*)p;
    GET(g_obj_probs, OBJ_PROBS, float)
    GET(g_fo, FO, float)
    GET(g_h_obj, HOBJ, float)
    GET(g_h_rel, HREL, float)
    GET(g_sumso, SUMSO, float)
    GET(g_m_rel, MREL, float)
    GET(g_hm, HM, float)
    GET(g_m_obj, MOBJ, float)
    GET(g_xw_rel, XWR, float)
    GET(g_hu_rel, HUR, float)
    GET(g_z_rel, ZR, float)
    GET(g_rh_rel, RHR, float)
    GET(g_nu_rel, NUR, float)
    GET(g_xw_obj, XWO, float)
    GET(g_hu_obj, HUO, float)
    GET(g_z_obj, ZO, float)
    GET(g_rh_obj, RHO, float)
    GET(g_nu_obj, NUO, float)
    GET(g_sp, SP, float)
    GET(g_keep, KEEP, unsigned char)
#undef GET
    g_sc.init = true;
}

extern "C" void kernel_launch(void* const* d_in, const int* in_sizes, int n_in,
                              void* d_out, int out_size) {
    (void)in_sizes; (void)n_in; (void)out_size;
    init_scratch();

    const float* obj_fmaps  = (const float*)d_in[1];
    const float* obj_logits = (const float*)d_in[2];
    const void*  rel_raw    = d_in[3];
    const float* vr         = (const float*)d_in[4];
    const float* boxes      = (const float*)d_in[5];
    const float* W_obj_proj = (const float*)d_in[6];
    const float* b_obj_proj = (const float*)d_in[7];
    const float* W_rel_proj = (const float*)d_in[8];
    const float* b_rel_proj = (const float*)d_in[9];
    const float* W_emb      = (const float*)d_in[10];
    const float* W_msg_rel  = (const float*)d_in[11];
    const float* W_msg_obj  = (const float*)d_in[12];
    const float* W_gru_obj  = (const float*)d_in[13];
    const float* U_gru_obj  = (const float*)d_in[14];
    const float* b_gru_obj  = (const float*)d_in[15];
    const float* W_gru_rel  = (const float*)d_in[16];
    const float* U_gru_rel  = (const float*)d_in[17];
    const float* b_gru_rel  = (const float*)d_in[18];
    const float* W_cls_rel  = (const float*)d_in[19];
    const float* b_cls_rel  = (const float*)d_in[20];
    const float* W_cls_obj  = (const float*)d_in[21];
    const float* b_cls_obj  = (const float*)d_in[22];

    float* out_obj_logits = (float*)d_out;                     // 512*151
    float* out_preds      = out_obj_logits + NN * NOC_;        // 512
    float* out_rel_logits = out_preds + NN;                    // 8192*51

    // 0. decode relation endpoint indices (int64 or int32 storage)
    decode_rel_kernel<<<1, 1024>>>(rel_raw);

    // 1. obj_probs = softmax(obj_logits)
    softmax_kernel<<<NN, 256>>>(obj_logits, g_sc.OBJ_PROBS);

    // 2. fo = obj_fmaps @ W_obj_proj + b
    sgemm(obj_fmaps, OBJD, W_obj_proj, HD, g_sc.FO, HD, NN, HD, OBJD, b_obj_proj, nullptr);

    // 3. h_obj = fo + obj_probs @ W_emb
    sgemm(g_sc.OBJ_PROBS, NOC_, W_emb, HD, g_sc.HOBJ, HD, NN, HD, NOC_, nullptr, g_sc.FO);

    // 4. h_rel = vr @ W_rel_proj + b   (the big 34 GFLOP GEMM)
    sgemm(vr, OBJD, W_rel_proj, HD, g_sc.HREL, HD, RR, HD, OBJD, b_rel_proj, nullptr);

    const int EW_REL_BLOCKS = (RR * HD + 255) / 256;
    const int EW_OBJ_BLOCKS = (NN * HD + 255) / 256;

    for (int t = 0; t < TSTEPS; t++) {
        // messages (all from pre-update states)
        gather_sum_kernel<<<EW_REL_BLOCKS, 256>>>(g_sc.HOBJ, g_sc.SUMSO);
        sgemm(g_sc.SUMSO, HD, W_msg_rel, HD, g_sc.MREL, HD, RR, HD, HD, nullptr, nullptr);
        sgemm(g_sc.HREL, HD, W_msg_obj, HD, g_sc.HM, HD, RR, HD, HD, nullptr, nullptr);
        scatter_obj_kernel<<<NN, 512>>>(g_sc.HM, g_sc.MOBJ);

        // GRU on relations: h_rel = GRU(h_rel, m_rel)
        sgemm(g_sc.MREL, HD, W_gru_rel, 3 * HD, g_sc.XWR, 3 * HD, RR, 3 * HD, HD, nullptr, nullptr);
        sgemm(g_sc.HREL, HD, U_gru_rel, 3 * HD, g_sc.HUR, 2 * HD, RR, 2 * HD, HD, nullptr, nullptr);
        gru_zr_kernel<<<EW_REL_BLOCKS, 256>>>(g_sc.XWR, g_sc.HUR, b_gru_rel, g_sc.HREL, g_sc.ZR, g_sc.RHR, RR);
        sgemm(g_sc.RHR, HD, U_gru_rel + 2 * HD, 3 * HD, g_sc.NUR, HD, RR, HD, HD, nullptr, nullptr);
        gru_fin_kernel<<<EW_REL_BLOCKS, 256>>>(g_sc.XWR, g_sc.NUR, b_gru_rel, g_sc.ZR, g_sc.HREL, RR);

        // GRU on objects: h_obj = GRU(h_obj, m_obj)
        sgemm(g_sc.MOBJ, HD, W_gru_obj, 3 * HD, g_sc.XWO, 3 * HD, NN, 3 * HD, HD, nullptr, nullptr);
        sgemm(g_sc.HOBJ, HD, U_gru_obj, 3 * HD, g_sc.HUO, 2 * HD, NN, 2 * HD, HD, nullptr, nullptr);
        gru_zr_kernel<<<EW_OBJ_BLOCKS, 256>>>(g_sc.XWO, g_sc.HUO, b_gru_obj, g_sc.HOBJ, g_sc.ZO, g_sc.RHO, NN);
        sgemm(g_sc.RHO, HD, U_gru_obj + 2 * HD, 3 * HD, g_sc.NUO, HD, NN, HD, HD, nullptr, nullptr);
        gru_fin_kernel<<<EW_OBJ_BLOCKS, 256>>>(g_sc.XWO, g_sc.NUO, b_gru_obj, g_sc.ZO, g_sc.HOBJ, NN);
    }

    // classifiers (write straight into d_out regions)
    sgemm(g_sc.HREL, HD, W_cls_rel, NRC_, out_rel_logits, NRC_, RR, NRC_, HD, b_cls_rel, nullptr);
    sgemm(g_sc.HOBJ, HD, W_cls_obj, NOC_, out_obj_logits, NOC_, NN, NOC_, HD, b_cls_obj, nullptr);

    // softmax -> NMS -> preds
    softmax_kernel<<<NN, 256>>>(out_obj_logits, g_sc.SP);
    nms_kernel<<<150, 512>>>(g_sc.SP, boxes, g_sc.KEEP);
    preds_kernel<<<(NN + 255) / 256, 256>>>(g_sc.SP, g_sc.KEEP, out_preds);
}

// round 3
// speedup vs baseline: 1.6554x; 1.6554x over previous
#include <cuda_runtime.h>
#include <cuda_bf16.h>
#include <math.h>
#include <stdint.h>

// ---------------- problem constants ----------------
#define BIMG 8
#define OPI_ 64
#define RPI_ 1024
#define NN 512            // N objects
#define RR 8192           // R relations
#define OBJD 4096
#define HD 512
#define NOC_ 151
#define NRC_ 51
#define TSTEPS 3
#define IOU_THR_ 0.3f

// ---------------- scratch (device globals; no runtime alloc allowed) -------
__device__ float g_obj_probs[NN * NOC_];
__device__ float g_fo[NN * HD];
__device__ float g_h_obj[NN * HD];
__device__ float g_h_rel[RR * HD];
__device__ float g_sumso[RR * HD];
__device__ float g_m_rel[RR * HD];
__device__ float g_hm[RR * HD];
__device__ float g_m_obj[NN * HD];
__device__ float g_xw_rel[RR * 3 * HD];
__device__ float g_hu_rel[RR * 2 * HD];
__device__ float g_z_rel[RR * HD];
__device__ float g_rh_rel[RR * HD];
__device__ float g_nu_rel[RR * HD];
__device__ float g_xw_obj[NN * 3 * HD];
__device__ float g_hu_obj[NN * 2 * HD];
__device__ float g_z_obj[NN * HD];
__device__ float g_rh_obj[NN * HD];
__device__ float g_nu_obj[NN * HD];
__device__ float g_sp[NN * NOC_];
__device__ unsigned char g_keep[150 * NN];
__device__ int g_s_idx[RR];
__device__ int g_o_idx[RR];

// ============================================================================
// 3xTF32 tensor-core GEMM: C = A@B (+bias)
// Requires: M%128==0, N%128==0, K%16==0, K>=32, lda/ldb multiples of 4.
// 128x128x16 tile, 256 threads (8 warps, 2x4), warp tile 64x32, cp.async
// double buffering. Accuracy ~= fp32 via hi/lo tf32 split (3 MMA passes).
// ============================================================================
#define BM 128
#define BN 128
#define BKT 16

__device__ __forceinline__ void split_tf32(float v, uint32_t& hi, uint32_t& lo) {
    uint32_t h;
    asm("cvt.rna.tf32.f32 %0, %1;" : "=r"(h) : "f"(v));
    float l = v - __uint_as_float(h);
    uint32_t lb;
    asm("cvt.rna.tf32.f32 %0, %1;" : "=r"(lb) : "f"(l));
    hi = h; lo = lb;
}

__device__ __forceinline__ void mma_tf32(float* c, const uint32_t* a, const uint32_t* b) {
    asm volatile(
        "mma.sync.aligned.m16n8k8.row.col.f32.tf32.tf32.f32 "
        "{%0,%1,%2,%3},{%4,%5,%6,%7},{%8,%9},{%0,%1,%2,%3};"
        : "+f"(c[0]), "+f"(c[1]), "+f"(c[2]), "+f"(c[3])
        : "r"(a[0]), "r"(a[1]), "r"(a[2]), "r"(a[3]), "r"(b[0]), "r"(b[1]));
}

__device__ __forceinline__ void cp16(uint32_t dst, const float* src) {
    asm volatile("cp.async.cg.shared.global [%0], [%1], 16;" :: "r"(dst), "l"(src));
}

__global__ __launch_bounds__(256) void tf32_gemm_kernel(
    const float* __restrict__ A, int lda,
    const float* __restrict__ B, int ldb,
    float* __restrict__ C, int ldc,
    int M, int N, int K,
    const float* __restrict__ bias)
{
    __shared__ float As[2][BM][BKT + 4];   // pad 4: conflict-free frag reads
    __shared__ float Bs[2][BKT][BN + 8];   // pad 8: conflict-free frag reads

    const int tid = threadIdx.x;
    const int lane = tid & 31;
    const int warp = tid >> 5;
    const int wm = warp >> 2;     // 0..1
    const int wn = warp & 3;      // 0..3
    const int lr = lane >> 2;     // 0..7
    const int lc = lane & 3;      // 0..3
    const int m0 = blockIdx.y * BM;
    const int n0 = blockIdx.x * BN;

    const int a_row = tid >> 2;          // +64 on 2nd pass
    const int a_c4  = (tid & 3) * 4;
    const int b_row = tid >> 5;          // +8 on 2nd pass
    const int b_c4  = (tid & 31) * 4;

    uint32_t sA = (uint32_t)__cvta_generic_to_shared(&As[0][0][0]);
    uint32_t sB = (uint32_t)__cvta_generic_to_shared(&Bs[0][0][0]);

    const int KT = K / BKT;

    float acc[4][4][4];
#pragma unroll
    for (int i = 0; i < 4; i++)
#pragma unroll
        for (int j = 0; j < 4; j++)
#pragma unroll
            for (int l = 0; l < 4; l++) acc[i][j][l] = 0.f;

    auto load_tiles = [&](int kt, int buf) {
        const int k0 = kt * BKT;
#pragma unroll
        for (int p = 0; p < 2; p++) {
            int r = a_row + p * 64;
            uint32_t dst = sA + (uint32_t)(((buf * BM + r) * (BKT + 4) + a_c4) * 4);
            cp16(dst, A + (size_t)(m0 + r) * lda + k0 + a_c4);
        }
#pragma unroll
        for (int p = 0; p < 2; p++) {
            int r = b_row + p * 8;
            uint32_t dst = sB + (uint32_t)(((buf * BKT + r) * (BN + 8) + b_c4) * 4);
            cp16(dst, B + (size_t)(k0 + r) * ldb + n0 + b_c4);
        }
        asm volatile("cp.async.commit_group;");
    };

    load_tiles(0, 0);
    load_tiles(1, 1);
    asm volatile("cp.async.wait_group 1;");
    __syncthreads();

    for (int kt = 0; kt < KT; kt++) {
        const int cur = kt & 1;
#pragma unroll
        for (int kk = 0; kk < BKT; kk += 8) {
            uint32_t aH[4][4], aL[4][4], bH[4][2], bL[4][2];
#pragma unroll
            for (int mt = 0; mt < 4; mt++) {
                int rb = wm * 64 + mt * 16;
                float v0 = As[cur][rb + lr][kk + lc];
                float v1 = As[cur][rb + lr + 8][kk + lc];
                float v2 = As[cur][rb + lr][kk + lc + 4];
                float v3 = As[cur][rb + lr + 8][kk + lc + 4];
                split_tf32(v0, aH[mt][0], aL[mt][0]);
                split_tf32(v1, aH[mt][1], aL[mt][1]);
                split_tf32(v2, aH[mt][2], aL[mt][2]);
                split_tf32(v3, aH[mt][3], aL[mt][3]);
            }
#pragma unroll
            for (int nt = 0; nt < 4; nt++) {
                int nc = wn * 32 + nt * 8 + lr;
                float u0 = Bs[cur][kk + lc][nc];
                float u1 = Bs[cur][kk + lc + 4][nc];
                split_tf32(u0, bH[nt][0], bL[nt][0]);
                split_tf32(u1, bH[nt][1], bL[nt][1]);
            }
#pragma unroll
            for (int mt = 0; mt < 4; mt++)
#pragma unroll
                for (int nt = 0; nt < 4; nt++) {
                    mma_tf32(acc[mt][nt], aH[mt], bH[nt]);  // hi*hi
                    mma_tf32(acc[mt][nt], aH[mt], bL[nt]);  // hi*lo
                    mma_tf32(acc[mt][nt], aL[mt], bH[nt]);  // lo*hi
                }
        }
        __syncthreads();
        if (kt + 2 < KT) {
            load_tiles(kt + 2, cur);
            asm volatile("cp.async.wait_group 1;");
        } else if (kt + 1 < KT) {
            asm volatile("cp.async.wait_group 0;");
        }
        __syncthreads();
    }

    // epilogue
#pragma unroll
    for (int mt = 0; mt < 4; mt++) {
        int gm0 = m0 + wm * 64 + mt * 16 + lr;
        int gm1 = gm0 + 8;
#pragma unroll
        for (int nt = 0; nt < 4; nt++) {
            int gn = n0 + wn * 32 + nt * 8 + lc * 2;
            float b0 = 0.f, b1 = 0.f;
            if (bias) { b0 = bias[gn]; b1 = bias[gn + 1]; }
            float2 v0 = make_float2(acc[mt][nt][0] + b0, acc[mt][nt][1] + b1);
            float2 v1 = make_float2(acc[mt][nt][2] + b0, acc[mt][nt][3] + b1);
            *(float2*)(C + (size_t)gm0 * ldc + gn) = v0;
            *(float2*)(C + (size_t)gm1 * ldc + gn) = v1;
        }
    }
}

// ---------------- generic fp32 SGEMM (small/odd shapes only) ----------------
__global__ __launch_bounds__(256) void sgemm_kernel(
    const float* __restrict__ A, int lda,
    const float* __restrict__ B, int ldb,
    float* __restrict__ C, int ldc,
    int M, int N, int K,
    const float* __restrict__ bias,
    const float* __restrict__ addm)
{
    __shared__ float As[8][132];
    __shared__ float Bs[8][128];
    const int tid = threadIdx.x;
    const int tx = tid & 15;
    const int ty = tid >> 4;
    const int m0 = blockIdx.y * 128;
    const int n0 = blockIdx.x * 128;

    float acc[8][8];
#pragma unroll
    for (int i = 0; i < 8; i++)
#pragma unroll
        for (int j = 0; j < 8; j++) acc[i][j] = 0.f;

    for (int k0 = 0; k0 < K; k0 += 8) {
#pragma unroll
        for (int l = 0; l < 4; l++) {
            int e = tid + l * 256;
            int r = e >> 3, c = e & 7;
            float v = 0.f;
            int gm = m0 + r, gk = k0 + c;
            if (gm < M && gk < K) v = A[(size_t)gm * lda + gk];
            As[c][r] = v;
        }
#pragma unroll
        for (int l = 0; l < 4; l++) {
            int e = tid + l * 256;
            int r = e >> 7, c = e & 127;
            float v = 0.f;
            int gk = k0 + r, gn = n0 + c;
            if (gk < K && gn < N) v = B[(size_t)gk * ldb + gn];
            Bs[r][c] = v;
        }
        __syncthreads();
#pragma unroll
        for (int k = 0; k < 8; k++) {
            float a[8], b[8];
#pragma unroll
            for (int i = 0; i < 8; i++) a[i] = As[k][ty * 8 + i];
#pragma unroll
            for (int j = 0; j < 8; j++) b[j] = Bs[k][tx * 8 + j];
#pragma unroll
            for (int i = 0; i < 8; i++)
#pragma unroll
                for (int j = 0; j < 8; j++)
                    acc[i][j] = fmaf(a[i], b[j], acc[i][j]);
        }
        __syncthreads();
    }
#pragma unroll
    for (int i = 0; i < 8; i++) {
        int gm = m0 + ty * 8 + i;
        if (gm >= M) continue;
#pragma unroll
        for (int j = 0; j < 8; j++) {
            int gn = n0 + tx * 8 + j;
            if (gn >= N) continue;
            float v = acc[i][j];
            if (bias) v += bias[gn];
            if (addm) v += addm[(size_t)gm * ldc + gn];
            C[(size_t)gm * ldc + gn] = v;
        }
    }
}

// ---------------- decode rel_inds (handles int64 OR int32 storage) ---------
__global__ __launch_bounds__(1024) void decode_rel_kernel(const void* rel_raw) {
    __shared__ int s_or;
    int tid = threadIdx.x;
    if (tid == 0) s_or = 0;
    __syncthreads();
    const int* v32 = (const int*)rel_raw;
    int acc = 0;
    for (int i = tid; i < (3 * RR) / 2; i += 1024) acc |= v32[2 * i + 1];
    if (acc) atomicOr(&s_or, 1);
    __syncthreads();
    bool is64 = (s_or == 0);
    if (is64) {
        const long long* v = (const long long*)rel_raw;
        for (int r = tid; r < RR; r += 1024) {
            g_s_idx[r] = (int)v[3 * r + 1];
            g_o_idx[r] = (int)v[3 * r + 2];
        }
    } else {
        for (int r = tid; r < RR; r += 1024) {
            g_s_idx[r] = v32[3 * r + 1];
            g_o_idx[r] = v32[3 * r + 2];
        }
    }
}

// ---------------- row softmax over NOC columns ------------------------------
__global__ void softmax_kernel(const float* __restrict__ X, float* __restrict__ Y) {
    int row = blockIdx.x;
    int tid = threadIdx.x;  // 256
    __shared__ float red[256];
    const float* x = X + (size_t)row * NOC_;
    float m = -3.4e38f;
    for (int c = tid; c < NOC_; c += 256) m = fmaxf(m, x[c]);
    red[tid] = m; __syncthreads();
    for (int s = 128; s > 0; s >>= 1) {
        if (tid < s) red[tid] = fmaxf(red[tid], red[tid + s]);
        __syncthreads();
    }
    m = red[0]; __syncthreads();
    float sum = 0.f;
    for (int c = tid; c < NOC_; c += 256) sum += expf(x[c] - m);
    red[tid] = sum; __syncthreads();
    for (int s = 128; s > 0; s >>= 1) {
        if (tid < s) red[tid] += red[tid + s];
        __syncthreads();
    }
    float inv = 1.f / red[0];
    for (int c = tid; c < NOC_; c += 256)
        Y[(size_t)row * NOC_ + c] = expf(x[c] - m) * inv;
}

// ---------------- SUMSO[r] = h_obj[s_r] + h_obj[o_r] ------------------------
__global__ void gather_sum_kernel(const float* __restrict__ Hobj, float* __restrict__ out) {
    int idx = blockIdx.x * blockDim.x + threadIdx.x;
    if (idx >= RR * HD) return;
    int r = idx >> 9;
    int c = idx & 511;
    int s = g_s_idx[r];
    int o = g_o_idx[r];
    out[idx] = Hobj[(size_t)s * HD + c] + Hobj[(size_t)o * HD + c];
}

// ---------------- m_obj scatter: deterministic block-per-object scan --------
__global__ __launch_bounds__(512) void scatter_obj_kernel(const float* __restrict__ HM,
                                                          float* __restrict__ MOBJ) {
    int obj = blockIdx.x;
    int c = threadIdx.x;
    int img = obj >> 6;
    int base = img * RPI_;
    __shared__ int ss[RPI_];
    __shared__ int oo[RPI_];
    for (int j = c; j < RPI_; j += 512) {
        ss[j] = g_s_idx[base + j];
        oo[j] = g_o_idx[base + j];
    }
    __syncthreads();
    float acc = 0.f;
    for (int j = 0; j < RPI_; j++) {
        if (ss[j] == obj) acc += HM[(size_t)(base + j) * HD + c];
        if (oo[j] == obj) acc += HM[(size_t)(base + j) * HD + c];
    }
    MOBJ[(size_t)obj * HD + c] = acc;
}

// ---------------- GRU elementwise: z, r*h ------------------------------------
__global__ void gru_zr_kernel(const float* __restrict__ XW, const float* __restrict__ HU,
                              const float* __restrict__ b, const float* __restrict__ Hh,
                              float* __restrict__ Z, float* __restrict__ RH, int M) {
    int idx = blockIdx.x * blockDim.x + threadIdx.x;
    if (idx >= M * HD) return;
    int row = idx >> 9;
    int c = idx & 511;
    float z = XW[(size_t)row * 1536 + c] + HU[(size_t)row * 1024 + c] + b[c];
    float r = XW[(size_t)row * 1536 + 512 + c] + HU[(size_t)row * 1024 + 512 + c] + b[512 + c];
    z = 1.f / (1.f + expf(-z));
    r = 1.f / (1.f + expf(-r));
    Z[idx] = z;
    RH[idx] = r * Hh[idx];
}

// ---------------- GRU elementwise: n, h update (in place) -------------------
__global__ void gru_fin_kernel(const float* __restrict__ XW, const float* __restrict__ NU,
                               const float* __restrict__ b, const float* __restrict__ Z,
                               float* __restrict__ Hh, int M) {
    int idx = blockIdx.x * blockDim.x + threadIdx.x;
    if (idx >= M * HD) return;
    int row = idx >> 9;
    int c = idx & 511;
    float n = tanhf(XW[(size_t)row * 1536 + 1024 + c] + NU[idx] + b[1024 + c]);
    float z = Z[idx];
    Hh[idx] = (1.f - z) * Hh[idx] + z * n;
}

// ---------------- NMS: one block per class (1..150) -------------------------
__global__ __launch_bounds__(512) void nms_kernel(const float* __restrict__ SP,
                                                  const float* __restrict__ BOX,
                                                  unsigned char* __restrict__ KEEP) {
    int cls = blockIdx.x + 1;
    int tid = threadIdx.x;
    __shared__ float sc[NN];
    __shared__ int sidx[NN];
    __shared__ float bx[NN][4];
    __shared__ float area[NN];
    __shared__ unsigned char keep[NN];

    sc[tid] = SP[(size_t)tid * NOC_ + cls];
    sidx[tid] = tid;
    __syncthreads();

    for (int k = 2; k <= NN; k <<= 1) {
        for (int j = k >> 1; j > 0; j >>= 1) {
            int ixj = tid ^ j;
            if (ixj > tid) {
                float s1 = sc[tid], s2 = sc[ixj];
                int i1 = sidx[tid], i2 = sidx[ixj];
                bool dir = ((tid & k) == 0);
                bool precBA = (s2 > s1) || (s2 == s1 && i2 < i1);
                if (precBA == dir) {
                    sc[tid] = s2; sc[ixj] = s1;
                    sidx[tid] = i2; sidx[ixj] = i1;
                }
            }
            __syncthreads();
        }
    }

    int oi = sidx[tid];
    float x1 = BOX[((size_t)oi * NOC_ + cls) * 4 + 0];
    float y1 = BOX[((size_t)oi * NOC_ + cls) * 4 + 1];
    float x2 = BOX[((size_t)oi * NOC_ + cls) * 4 + 2];
    float y2 = BOX[((size_t)oi * NOC_ + cls) * 4 + 3];
    bx[tid][0] = x1; bx[tid][1] = y1; bx[tid][2] = x2; bx[tid][3] = y2;
    area[tid] = (x2 - x1) * (y2 - y1);
    keep[tid] = 1;
    __syncthreads();

    for (int i = 0; i < NN - 1; i++) {
        if (tid > i && keep[i] && keep[tid]) {
            float lx = fmaxf(bx[i][0], x1);
            float ly = fmaxf(bx[i][1], y1);
            float rx = fminf(bx[i][2], x2);
            float ry = fminf(bx[i][3], y2);
            float w = fmaxf(rx - lx, 0.f);
            float h = fmaxf(ry - ly, 0.f);
            float inter = w * h;
            float iou = inter / (area[i] + area[tid] - inter + 1e-9f);
            if (iou > IOU_THR_) keep[tid] = 0;
        }
        __syncthreads();
    }
    KEEP[(size_t)(cls - 1) * NN + oi] = keep[tid];
}

// ---------------- obj_preds: argmax over kept class scores ------------------
__global__ void preds_kernel(const float* __restrict__ SP, const unsigned char* __restrict__ KEEP,
                             float* __restrict__ out) {
    int n = blockIdx.x * blockDim.x + threadIdx.x;
    if (n >= NN) return;
    float best = -1.f;
    int bi = 0;
    for (int c = 0; c < 150; c++) {
        float v = KEEP[(size_t)c * NN + n] ? SP[(size_t)n * NOC_ + c + 1] : 0.f;
        if (v > best) { best = v; bi = c; }
    }
    out[n] = (float)(bi + 1);
}

// ---------------- host orchestration ----------------------------------------
static void sgemm(const float* A, int lda, const float* B, int ldb,
                  float* C, int ldc, int M, int N, int K,
                  const float* bias, const float* addm) {
    dim3 g((N + 127) / 128, (M + 127) / 128);
    sgemm_kernel<<<g, 256>>>(A, lda, B, ldb, C, ldc, M, N, K, bias, addm);
}

// tensor-core path: M%128==0, N%128==0, K%16==0 (call sites guarantee this)
static void tgemm(const float* A, int lda, const float* B, int ldb,
                  float* C, int ldc, int M, int N, int K,
                  const float* bias) {
    dim3 g(N / 128, M / 128);
    tf32_gemm_kernel<<<g, 256>>>(A, lda, B, ldb, C, ldc, M, N, K, bias);
}

struct Scratch {
    float *OBJ_PROBS, *FO, *HOBJ, *HREL, *SUMSO, *MREL, *HM, *MOBJ;
    float *XWR, *HUR, *ZR, *RHR, *NUR, *XWO, *HUO, *ZO, *RHO, *NUO, *SP;
    unsigned char* KEEP;
    bool init = false;
};
static Scratch g_sc;

static void init_scratch() {
    if (g_sc.init) return;
    void* p;
#define GET(sym, fld, T) cudaGetSymbolAddress(&p, sym); g_sc.fld = (T*)p;
    GET(g_obj_probs, OBJ_PROBS, float)
    GET(g_fo, FO, float)
    GET(g_h_obj, HOBJ, float)
    GET(g_h_rel, HREL, float)
    GET(g_sumso, SUMSO, float)
    GET(g_m_rel, MREL, float)
    GET(g_hm, HM, float)
    GET(g_m_obj, MOBJ, float)
    GET(g_xw_rel, XWR, float)
    GET(g_hu_rel, HUR, float)
    GET(g_z_rel, ZR, float)
    GET(g_rh_rel, RHR, float)
    GET(g_nu_rel, NUR, float)
    GET(g_xw_obj, XWO, float)
    GET(g_hu_obj, HUO, float)
    GET(g_z_obj, ZO, float)
    GET(g_rh_obj, RHO, float)
    GET(g_nu_obj, NUO, float)
    GET(g_sp, SP, float)
    GET(g_keep, KEEP, unsigned char)
#undef GET
    g_sc.init = true;
}

extern "C" void kernel_launch(void* const* d_in, const int* in_sizes, int n_in,
                              void* d_out, int out_size) {
    (void)in_sizes; (void)n_in; (void)out_size;
    init_scratch();

    const float* obj_fmaps  = (const float*)d_in[1];
    const float* obj_logits = (const float*)d_in[2];
    const void*  rel_raw    = d_in[3];
    const float* vr         = (const float*)d_in[4];
    const float* boxes      = (const float*)d_in[5];
    const float* W_obj_proj = (const float*)d_in[6];
    const float* b_obj_proj = (const float*)d_in[7];
    const float* W_rel_proj = (const float*)d_in[8];
    const float* b_rel_proj = (const float*)d_in[9];
    const float* W_emb      = (const float*)d_in[10];
    const float* W_msg_rel  = (const float*)d_in[11];
    const float* W_msg_obj  = (const float*)d_in[12];
    const float* W_gru_obj  = (const float*)d_in[13];
    const float* U_gru_obj  = (const float*)d_in[14];
    const float* b_gru_obj  = (const float*)d_in[15];
    const float* W_gru_rel  = (const float*)d_in[16];
    const float* U_gru_rel  = (const float*)d_in[17];
    const float* b_gru_rel  = (const float*)d_in[18];
    const float* W_cls_rel  = (const float*)d_in[19];
    const float* b_cls_rel  = (const float*)d_in[20];
    const float* W_cls_obj  = (const float*)d_in[21];
    const float* b_cls_obj  = (const float*)d_in[22];

    float* out_obj_logits = (float*)d_out;                 // 512*151
    float* out_preds      = out_obj_logits + NN * NOC_;    // 512
    float* out_rel_logits = out_preds + NN;                // 8192*51

    // 0. decode relation endpoint indices
    decode_rel_kernel<<<1, 1024>>>(rel_raw);

    // 1. obj_probs = softmax(obj_logits)
    softmax_kernel<<<NN, 256>>>(obj_logits, g_sc.OBJ_PROBS);

    // 2. fo = obj_fmaps @ W_obj_proj + b           [512,512,4096] tensor
    tgemm(obj_fmaps, OBJD, W_obj_proj, HD, g_sc.FO, HD, NN, HD, OBJD, b_obj_proj);

    // 3. h_obj = fo + obj_probs @ W_emb            [K=151 -> SIMT, addm]
    sgemm(g_sc.OBJ_PROBS, NOC_, W_emb, HD, g_sc.HOBJ, HD, NN, HD, NOC_, nullptr, g_sc.FO);

    // 4. h_rel = vr @ W_rel_proj + b               [8192,512,4096] tensor
    tgemm(vr, OBJD, W_rel_proj, HD, g_sc.HREL, HD, RR, HD, OBJD, b_rel_proj);

    const int EW_REL_BLOCKS = (RR * HD + 255) / 256;
    const int EW_OBJ_BLOCKS = (NN * HD + 255) / 256;

    for (int t = 0; t < TSTEPS; t++) {
        // messages (all from pre-update states)
        gather_sum_kernel<<<EW_REL_BLOCKS, 256>>>(g_sc.HOBJ, g_sc.SUMSO);
        tgemm(g_sc.SUMSO, HD, W_msg_rel, HD, g_sc.MREL, HD, RR, HD, HD, nullptr);
        tgemm(g_sc.HREL, HD, W_msg_obj, HD, g_sc.HM, HD, RR, HD, HD, nullptr);
        scatter_obj_kernel<<<NN, 512>>>(g_sc.HM, g_sc.MOBJ);

        // GRU on relations
        tgemm(g_sc.MREL, HD, W_gru_rel, 3 * HD, g_sc.XWR, 3 * HD, RR, 3 * HD, HD, nullptr);
        tgemm(g_sc.HREL, HD, U_gru_rel, 3 * HD, g_sc.HUR, 2 * HD, RR, 2 * HD, HD, nullptr);
        gru_zr_kernel<<<EW_REL_BLOCKS, 256>>>(g_sc.XWR, g_sc.HUR, b_gru_rel, g_sc.HREL, g_sc.ZR, g_sc.RHR, RR);
        tgemm(g_sc.RHR, HD, U_gru_rel + 2 * HD, 3 * HD, g_sc.NUR, HD, RR, HD, HD, nullptr);
        gru_fin_kernel<<<EW_REL_BLOCKS, 256>>>(g_sc.XWR, g_sc.NUR, b_gru_rel, g_sc.ZR, g_sc.HREL, RR);

        // GRU on objects
        tgemm(g_sc.MOBJ, HD, W_gru_obj, 3 * HD, g_sc.XWO, 3 * HD, NN, 3 * HD, HD, nullptr);
        tgemm(g_sc.HOBJ, HD, U_gru_obj, 3 * HD, g_sc.HUO, 2 * HD, NN, 2 * HD, HD, nullptr);
        gru_zr_kernel<<<EW_OBJ_BLOCKS, 256>>>(g_sc.XWO, g_sc.HUO, b_gru_obj, g_sc.HOBJ, g_sc.ZO, g_sc.RHO, NN);
        tgemm(g_sc.RHO, HD, U_gru_obj + 2 * HD, 3 * HD, g_sc.NUO, HD, NN, HD, HD, nullptr);
        gru_fin_kernel<<<EW_OBJ_BLOCKS, 256>>>(g_sc.XWO, g_sc.NUO, b_gru_obj, g_sc.ZO, g_sc.HOBJ, NN);
    }

    // classifiers (odd N -> SIMT)
    sgemm(g_sc.HREL, HD, W_cls_rel, NRC_, out_rel_logits, NRC_, RR, NRC_, HD, b_cls_rel, nullptr);
    sgemm(g_sc.HOBJ, HD, W_cls_obj, NOC_, out_obj_logits, NOC_, NN, NOC_, HD, b_cls_obj, nullptr);

    // softmax -> NMS -> preds
    softmax_kernel<<<NN, 256>>>(out_obj_logits, g_sc.SP);
    nms_kernel<<<150, 512>>>(g_sc.SP, boxes, g_sc.KEEP);
    preds_kernel<<<(NN + 255) / 256, 256>>>(g_sc.SP, g_sc.KEEP, out_preds);
}